// round 12
// baseline (speedup 1.0000x reference)
#include <cuda_runtime.h>
#include <cuda_fp16.h>
#include <cstdint>

// GoalDecoderLSTM, B=131072, H=64, E=16, SEQ=30 — fp16 HMMA.
// R12 = R11 (B in registers, ldmatrix A, fp32 tanh.approx epilogue, parallel
// tail, m-stagger, occ 2) + software pipelining:
//   * per-step schedule  MMA(mm) -> LDSM(mm+1) -> EPI(mm)   (single A buffer)
//   * cross-barrier prefetch: LDSM kc0..3 of next step's mm=0 before the tail
//     (h-part of N complete at barrier A; tail only writes kc4 words 32..39),
//     kc4 after barrier B.
//   * tail constants (cv, M2, goc) in registers.
// CTA = 64 elems, 8 warps, occ 2. Warp w owns j in [8w,8w+8) (all 4 gates).

#define TB    64
#define SEQ   30
#define NTHR  256
#define HROW  44

// SMEM layout
#define SM_H       0                        // 2 bufs * 64*44*4 = 2*11264
#define HBUF_BYTES (TB * HROW * 4)
#define SM_F       (2*HBUF_BYTES)           // 22528
// float indices within sF
#define FI_BC    0      // 256
#define FI_W2P   256    // 128
#define FI_MG    384    // 128
#define FI_M2    512    // 4
#define FI_CV    516    // 2
#define FI_CG    518    // 2
#define FI_WSE4  520    // 32
#define FI_BSE2  552    // 16
#define FI_RELP  568    // 8 warps * 65 float2 = 1040 floats
#define RELPW    130    // floats per warp slot (padded: breaks 128-word alias)
#define FI_AB    (FI_RELP + 8*RELPW)   // 128 floats
#define FI_GOC   (FI_AB + 128)         // 128 floats
#define SF_FLOATS (FI_GOC + 128)
#define SMEM_BYTES (SM_F + SF_FLOATS*4)

typedef uint32_t u32;
typedef unsigned long long u64;

// ---- device staging (prep -> main) ----
__device__ __align__(16) u64 g_Bfrag[160 * 32];   // frag f = wid*20 + kc*4 + t
__device__ float g_bc[256];
__device__ float g_w2p[128];
__device__ float g_Mg[128];
__device__ float g_M2[4];
__device__ float g_cv[2];
__device__ float g_cg[2];
__device__ float g_wse4[32];
__device__ float g_bse2[16];

// ---- helpers ----
__device__ __forceinline__ u32 f16pack(float a, float b) {
    __half2 h = __floats2half2_rn(a, b);    // a -> low, b -> high
    return *(u32*)&h;
}
__device__ __forceinline__ void mma16816(float* d, const u32* a, u32 b0, u32 b1) {
    asm volatile("mma.sync.aligned.m16n8k16.row.col.f32.f16.f16.f32 "
        "{%0,%1,%2,%3}, {%4,%5,%6,%7}, {%8,%9}, {%0,%1,%2,%3};"
        : "+f"(d[0]), "+f"(d[1]), "+f"(d[2]), "+f"(d[3])
        : "r"(a[0]), "r"(a[1]), "r"(a[2]), "r"(a[3]), "r"(b0), "r"(b1));
}
__device__ __forceinline__ void ldsm_x4(u32* a, u32 addr) {
    asm volatile("ldmatrix.sync.aligned.m8n8.x4.shared.b16 {%0,%1,%2,%3}, [%4];"
        : "=r"(a[0]), "=r"(a[1]), "=r"(a[2]), "=r"(a[3]) : "r"(addr));
}
__device__ __forceinline__ float tanh_hw(float x) {
    float r; asm("tanh.approx.f32 %0, %1;" : "=f"(r) : "f"(x)); return r;
}
__device__ __forceinline__ float lstm_unit(float iv, float fv, float gv, float ov, float& cst) {
    float si = fmaf(0.5f, tanh_hw(0.5f * iv), 0.5f);
    float sf = fmaf(0.5f, tanh_hw(0.5f * fv), 0.5f);
    float tg = tanh_hw(gv);
    float so = fmaf(0.5f, tanh_hw(0.5f * ov), 0.5f);
    float cn = fmaf(sf, cst, si * tg);
    cst = cn;
    return so * tanh_hw(cn);
}

// ============================================================================
// Prep: fold small matrices; build B fragments (fp16, per-warp-slice order)
// ============================================================================
__global__ void prep_kernel(const float* __restrict__ W_ih, const float* __restrict__ W_hh,
                            const float* __restrict__ b_ih, const float* __restrict__ b_hh,
                            const float* __restrict__ W_h2p, const float* __restrict__ b_h2p,
                            const float* __restrict__ W_goal, const float* __restrict__ b_goal,
                            const float* __restrict__ W_abs, const float* __restrict__ b_abs,
                            const float* __restrict__ W_se, const float* __restrict__ b_se)
{
    int tid = threadIdx.x;
    // frag f = w*20 + kc*4 + t  (w = warp slice 0..7, j in [8w, 8w+8))
    for (int idx = tid; idx < 160 * 32; idx += NTHR) {
        int f = idx >> 5, l = idx & 31;
        int w = f / 20, r = f % 20, kc = r >> 2, t = r & 3;
        int jj = l >> 2, c4 = l & 3;
        int j = 8 * w + jj;
        int row = t * 64 + j;
        int k0 = 16 * kc + 2 * c4;
        float v[4];
        #pragma unroll
        for (int i = 0; i < 4; i++) {
            int k = k0 + (i & 1) + (i >> 1) * 8;
            v[i] = (k < 64) ? W_hh[row * 64 + k] : W_ih[row * 16 + (k - 64)];
        }
        __half2 p0 = __floats2half2_rn(v[0], v[1]);
        __half2 p1 = __floats2half2_rn(v[2], v[3]);
        g_Bfrag[idx] = (u64)*(u32*)&p0 | ((u64)*(u32*)&p1 << 32);
    }
    {
        int j = tid & 63, t = tid >> 6, row = t * 64 + j;
        g_bc[tid] = b_ih[row] + b_hh[row];
    }
    if (tid < 64) {
        g_w2p[2 * tid]     = W_h2p[tid];
        g_w2p[2 * tid + 1] = W_h2p[192 + tid];
    }
    if (tid < 128) {
        int r = tid >> 6, j = tid & 63;
        float s = 0.f;
        for (int m = 0; m < 64; m++) s += W_h2p[r * 192 + 128 + m] * W_goal[m * 64 + j];
        g_Mg[tid] = s;
    }
    if (tid < 4) {
        int r = tid >> 1, c = tid & 1;
        float s = 0.f;
        for (int m = 0; m < 64; m++) s += W_h2p[r * 192 + 64 + m] * W_abs[m * 2 + c];
        g_M2[tid] = s;
    }
    if (tid < 2) {
        float s = b_h2p[tid];
        for (int m = 0; m < 64; m++) s += W_h2p[tid * 192 + 64 + m] * b_abs[m];
        g_cv[tid] = s;
        float s2 = 0.f;
        for (int m = 0; m < 64; m++) s2 += W_h2p[tid * 192 + 128 + m] * b_goal[m];
        g_cg[tid] = s2;
    }
    if (tid < 8) {
        g_wse4[tid * 4 + 0] = W_se[(2 * tid) * 2 + 0];
        g_wse4[tid * 4 + 1] = W_se[(2 * tid) * 2 + 1];
        g_wse4[tid * 4 + 2] = W_se[(2 * tid + 1) * 2 + 0];
        g_wse4[tid * 4 + 3] = W_se[(2 * tid + 1) * 2 + 1];
        g_bse2[tid * 2 + 0] = b_se[2 * tid];
        g_bse2[tid * 2 + 1] = b_se[2 * tid + 1];
    }
}

// ============================================================================
// Main kernel: 64 elems/CTA, 8 warps, 2 CTAs/SM, B in registers
// ============================================================================
__global__ void __launch_bounds__(NTHR, 2)
lstm_main(const float* __restrict__ traj_abs, const float* __restrict__ traj_rel,
          const float* __restrict__ h0g, const float* __restrict__ c0g,
          const float* __restrict__ goals, float* __restrict__ out, int Btot)
{
    extern __shared__ __align__(16) char smem[];
    float* sF = (float*)(smem + SM_F);
    const int tid = threadIdx.x, l = tid & 31, wid = tid >> 5;
    const int c4 = l & 3, q = l >> 2;
    const int b0 = blockIdx.x * TB;

    // ---- fill sF from staging ----
    for (int i = tid; i < 256; i += NTHR) sF[FI_BC + i] = g_bc[i];
    if (tid < 128) { sF[FI_W2P + tid] = g_w2p[tid]; sF[FI_MG + tid] = g_Mg[tid]; }
    if (tid < 4)  sF[FI_M2 + tid] = g_M2[tid];
    if (tid < 2)  { sF[FI_CV + tid] = g_cv[tid]; sF[FI_CG + tid] = g_cg[tid]; }
    if (tid < 32) sF[FI_WSE4 + tid] = g_wse4[tid];
    if (tid < 16) sF[FI_BSE2 + tid] = g_bse2[tid];
    __syncthreads();

    // ---- B fragments into registers (persistent) ----
    u64 Breg[5][4];
    {
        const u64* gB = g_Bfrag + (size_t)wid * 20 * 32 + l;
        #pragma unroll
        for (int kc = 0; kc < 5; kc++)
            #pragma unroll
            for (int t = 0; t < 4; t++)
                Breg[kc][t] = gB[(kc * 4 + t) * 32];
    }
    // per-warp-lane constants: biases + w2 pairs for j0 = 8*wid + 2*c4
    const int j0 = 8 * wid + 2 * c4;
    const float2 bI = *(const float2*)(sF + FI_BC + j0);
    const float2 bF = *(const float2*)(sF + FI_BC + 64 + j0);
    const float2 bG = *(const float2*)(sF + FI_BC + 128 + j0);
    const float2 bO = *(const float2*)(sF + FI_BC + 192 + j0);
    const float4 w2q = *(const float4*)(sF + FI_W2P + 2 * j0);
    const int wp = 4 * wid + c4;            // h' store word position (plain)

    // u32 shared base of H buffers
    const u32 Hbase = (u32)__cvta_generic_to_shared(smem);

    // per-mm offsets (m = (mm+wid)&3 stagger)
    int aofs[4], hoff[4], roff[4];
    {
        const int lrow_loc = ((l >> 3) & 1) * 8 + (l & 7);
        const int khalf = l >> 4;
        #pragma unroll
        for (int mm = 0; mm < 4; mm++) {
            int m = (mm + wid) & 3;
            aofs[mm] = (16 * m + lrow_loc) * (HROW * 4) + khalf * 16;
            hoff[mm] = (16 * m + q) * HROW + wp;
            roff[mm] = 16 * m + q;
        }
    }

    // ---- init H buffer 0 (plain fp16x2 word layout) ----
    {
        u32* H0 = (u32*)(smem + SM_H);
        for (int idx = tid; idx < TB * 32; idx += NTHR) {
            int row = idx >> 5, w = idx & 31;
            float2 hv = *(const float2*)(h0g + (size_t)(b0 + row) * 64 + 2 * w);
            H0[row * HROW + w] = f16pack(hv.x, hv.y);
        }
        for (int idx = tid; idx < TB * 8; idx += NTHR) {
            int row = idx >> 3, p = idx & 7;
            float2 tr = *(const float2*)(traj_rel + (size_t)(b0 + row) * 2);
            float4 w4 = *(const float4*)(sF + FI_WSE4 + 4 * p);
            float xa = w4.x * tr.x + w4.y * tr.y + sF[FI_BSE2 + 2 * p];
            float xb = w4.z * tr.x + w4.w * tr.y + sF[FI_BSE2 + 2 * p + 1];
            xa = (xa > 0.f) ? xa : 0.01f * xa;
            xb = (xb > 0.f) ? xb : 0.01f * xb;
            H0[row * HROW + 32 + p] = f16pack(xa, xb);
        }
    }

    // ---- c-state: creg[mm][rh][jj] ----
    float creg[4][2][2];
    #pragma unroll
    for (int mm = 0; mm < 4; mm++)
        #pragma unroll
        for (int rh = 0; rh < 2; rh++) {
            int row = roff[mm] + 8 * rh;
            float2 cv2 = *(const float2*)(c0g + (size_t)(b0 + row) * 64 + j0);
            creg[mm][rh][0] = cv2.x; creg[mm][rh][1] = cv2.y;
        }

    // ---- row-owner derived state -> SMEM (tid < 64, row = tid) ----
    if (tid < TB) {
        const int row = tid;
        sF[FI_AB + 2 * row]     = traj_abs[(size_t)(b0 + row) * 2];
        sF[FI_AB + 2 * row + 1] = traj_abs[(size_t)(b0 + row) * 2 + 1];
        float s0 = sF[FI_CG], s1 = sF[FI_CG + 1];
        const float* gp = goals + (size_t)(b0 + row) * 64;
        #pragma unroll 8
        for (int k = 0; k < 64; k++) {
            float gv = gp[k];
            s0 += sF[FI_MG + k] * gv;
            s1 += sF[FI_MG + 64 + k] * gv;
        }
        sF[FI_GOC + 2 * row] = s0; sF[FI_GOC + 2 * row + 1] = s1;
    }
    __syncthreads();

    // ---- tail constants in registers ----
    const int trow = tid >> 2;           // tail: row owned by this thread
    const int tpart = tid & 3;           // tail: which partial pair
    const float cv0 = sF[FI_CV], cv1 = sF[FI_CV + 1];
    const float m200 = sF[FI_M2], m201 = sF[FI_M2 + 1];
    const float m210 = sF[FI_M2 + 2], m211 = sF[FI_M2 + 3];
    const float goc0 = sF[FI_GOC + 2 * trow], goc1 = sF[FI_GOC + 2 * trow + 1];
    const float4 wse_a = *(const float4*)(sF + FI_WSE4 + 4 * (2 * tpart));
    const float4 wse_b = *(const float4*)(sF + FI_WSE4 + 4 * (2 * tpart + 1));
    const float2 bse_a = *(const float2*)(sF + FI_BSE2 + 2 * (2 * tpart));
    const float2 bse_b = *(const float2*)(sF + FI_BSE2 + 2 * (2 * tpart + 1));

    // ---- prologue: A fragments for mm=0 of H_0 ----
    u32 A[5][4];
    {
        const u32 ab = Hbase + aofs[0];
        #pragma unroll
        for (int kc = 0; kc < 5; kc++)
            ldsm_x4(A[kc], ab + kc * 32);
    }

    #pragma unroll 1
    for (int s = 0; s < SEQ; s++) {
        const u32 Hu = Hbase + (s & 1) * HBUF_BYTES;
        const u32 Nu = Hbase + ((s + 1) & 1) * HBUF_BYTES;
        u32* N = (u32*)(smem + SM_H) + ((s + 1) & 1) * (HBUF_BYTES / 4);

        #pragma unroll
        for (int mm = 0; mm < 4; mm++) {
            // ---- MMA on current A (bias-initialized accumulators) ----
            float acc[4][4] = {
                { bI.x, bI.y, bI.x, bI.y },
                { bF.x, bF.y, bF.x, bF.y },
                { bG.x, bG.y, bG.x, bG.y },
                { bO.x, bO.y, bO.x, bO.y },
            };
            #pragma unroll
            for (int kc = 0; kc < 5; kc++)
                #pragma unroll
                for (int t = 0; t < 4; t++)
                    mma16816(acc[t], A[kc], (u32)Breg[kc][t], (u32)(Breg[kc][t] >> 32));

            // ---- prefetch next m-tile's A (hides LDSM latency under epilogue) ----
            if (mm < 3) {
                const u32 ab = Hu + aofs[mm + 1];
                #pragma unroll
                for (int kc = 0; kc < 5; kc++)
                    ldsm_x4(A[kc], ab + kc * 32);
            }

            // ---- epilogue ----
            float rpm[2][2];
            #pragma unroll
            for (int rh = 0; rh < 2; rh++) {
                float h0v = lstm_unit(acc[0][2 * rh], acc[1][2 * rh],
                                      acc[2][2 * rh], acc[3][2 * rh], creg[mm][rh][0]);
                float h1v = lstm_unit(acc[0][2 * rh + 1], acc[1][2 * rh + 1],
                                      acc[2][2 * rh + 1], acc[3][2 * rh + 1], creg[mm][rh][1]);
                rpm[rh][0] = w2q.x * h0v + w2q.z * h1v;
                rpm[rh][1] = w2q.y * h0v + w2q.w * h1v;
                N[hoff[mm] + 8 * HROW * rh] = f16pack(h0v, h1v);
            }
            // quad butterfly -> warp partial for this warp's 8 j's
            #pragma unroll
            for (int rh = 0; rh < 2; rh++) {
                #pragma unroll
                for (int ax = 0; ax < 2; ax++) {
                    float v = rpm[rh][ax];
                    v += __shfl_xor_sync(0xFFFFFFFFu, v, 1);
                    v += __shfl_xor_sync(0xFFFFFFFFu, v, 2);
                    rpm[rh][ax] = v;
                }
            }
            if (c4 == 0) {
                #pragma unroll
                for (int rh = 0; rh < 2; rh++) {
                    int row = roff[mm] + 8 * rh;
                    *(float2*)(sF + FI_RELP + wid * RELPW + 2 * row) =
                        make_float2(rpm[rh][0], rpm[rh][1]);
                }
            }
        }
        __syncthreads();   // barrier A: h' + RELP visible

        // ---- prefetch next step's mm=0 A, h-part only (kc0..3; N h-part done,
        //      tail writes only words 32..39 of each row -> disjoint) ----
        if (s < SEQ - 1) {
            const u32 ab = Nu + aofs[0];
            #pragma unroll
            for (int kc = 0; kc < 4; kc++)
                ldsm_x4(A[kc], ab + kc * 32);
        }

        // ---- rel finalization: 4 threads per row (row=tid>>2, part=tid&3) ----
        {
            float2 pa = *(const float2*)(sF + FI_RELP + (2 * tpart) * RELPW + 2 * trow);
            float2 pb = *(const float2*)(sF + FI_RELP + (2 * tpart + 1) * RELPW + 2 * trow);
            float r0 = pa.x + pb.x, r1 = pa.y + pb.y;
            r0 += __shfl_xor_sync(0xFFFFFFFFu, r0, 1);
            r0 += __shfl_xor_sync(0xFFFFFFFFu, r0, 2);
            r1 += __shfl_xor_sync(0xFFFFFFFFu, r1, 1);
            r1 += __shfl_xor_sync(0xFFFFFFFFu, r1, 2);
            float a0 = sF[FI_AB + 2 * trow], a1 = sF[FI_AB + 2 * trow + 1];
            r0 += cv0 + goc0 + m200 * a0 + m201 * a1;
            r1 += cv1 + goc1 + m210 * a0 + m211 * a1;
            if (tpart == 0) {
                *(float2*)(out + ((size_t)s * Btot + b0 + trow) * 2) = make_float2(r0, r1);
                sF[FI_AB + 2 * trow] = a0 + r0;
                sF[FI_AB + 2 * trow + 1] = a1 + r1;
            }
            if (s < SEQ - 1) {
                float xa = wse_a.x * r0 + wse_a.y * r1 + bse_a.x;
                float xb = wse_a.z * r0 + wse_a.w * r1 + bse_a.y;
                xa = (xa > 0.f) ? xa : 0.01f * xa;
                xb = (xb > 0.f) ? xb : 0.01f * xb;
                N[trow * HROW + 32 + 2 * tpart] = f16pack(xa, xb);
                float xc = wse_b.x * r0 + wse_b.y * r1 + bse_b.x;
                float xd = wse_b.z * r0 + wse_b.w * r1 + bse_b.y;
                xc = (xc > 0.f) ? xc : 0.01f * xc;
                xd = (xd > 0.f) ? xd : 0.01f * xd;
                N[trow * HROW + 32 + 2 * tpart + 1] = f16pack(xc, xd);
            }
        }
        __syncthreads();   // barrier B: x' visible

        // ---- complete next step's mm=0 A: kc4 (x chunk) ----
        if (s < SEQ - 1)
            ldsm_x4(A[4], Nu + aofs[0] + 4 * 32);
    }
}

// ============================================================================
extern "C" void kernel_launch(void* const* d_in, const int* in_sizes, int n_in,
                              void* d_out, int out_size)
{
    const float* traj_abs = (const float*)d_in[0];
    const float* traj_rel = (const float*)d_in[1];
    const float* h0       = (const float*)d_in[2];
    const float* c0       = (const float*)d_in[3];
    const float* goals    = (const float*)d_in[4];
    const float* W_ih     = (const float*)d_in[5];
    const float* W_hh     = (const float*)d_in[6];
    const float* b_ih     = (const float*)d_in[7];
    const float* b_hh     = (const float*)d_in[8];
    const float* W_se     = (const float*)d_in[9];
    const float* b_se     = (const float*)d_in[10];
    const float* W_h2p    = (const float*)d_in[11];
    const float* b_h2p    = (const float*)d_in[12];
    const float* W_goal   = (const float*)d_in[13];
    const float* b_goal   = (const float*)d_in[14];
    const float* W_abs    = (const float*)d_in[15];
    const float* b_abs    = (const float*)d_in[16];

    int B = in_sizes[2] / 64;

    cudaFuncSetAttribute(lstm_main, cudaFuncAttributeMaxDynamicSharedMemorySize, SMEM_BYTES);

    prep_kernel<<<1, NTHR>>>(W_ih, W_hh, b_ih, b_hh, W_h2p, b_h2p,
                             W_goal, b_goal, W_abs, b_abs, W_se, b_se);
    lstm_main<<<B / TB, NTHR, SMEM_BYTES>>>(traj_abs, traj_rel, h0, c0, goals,
                                            (float*)d_out, B);
}

// round 13
// speedup vs baseline: 1.0497x; 1.0497x over previous
#include <cuda_runtime.h>
#include <cuda_fp16.h>
#include <cstdint>

// GoalDecoderLSTM, B=131072, H=64, E=16, SEQ=30 — fp16 HMMA.
// R13 = R11 (B in registers, ldmatrix A, fp32 tanh.approx epilogue, parallel
// tail, m-stagger, occ 2) + lean tail:
//   * tail constants (cv, M2, goc, wse, bse) hoisted to registers
//   * abs-position kept in per-thread registers (all 4 tail threads of a row
//     compute identical rel -> identical private ab updates; no SMEM AB)
// CTA = 64 elems, 8 warps, occ 2. Warp w owns j in [8w,8w+8) (all 4 gates).

#define TB    64
#define SEQ   30
#define NTHR  256
#define HROW  44

// SMEM layout
#define SM_H       0                        // 2 bufs * 64*44*4 = 2*11264
#define HBUF_BYTES (TB * HROW * 4)
#define SM_F       (2*HBUF_BYTES)           // 22528
// float indices within sF
#define FI_BC    0      // 256
#define FI_W2P   256    // 128
#define FI_MG    384    // 128
#define FI_M2    512    // 4
#define FI_CV    516    // 2
#define FI_CG    518    // 2
#define FI_WSE4  520    // 32
#define FI_BSE2  552    // 16
#define FI_RELP  568    // 8 warps * 65 float2 = 1040 floats
#define RELPW    130    // floats per warp slot (padded: breaks 128-word alias)
#define FI_GOC   (FI_RELP + 8*RELPW)   // 128 floats
#define SF_FLOATS (FI_GOC + 128)
#define SMEM_BYTES (SM_F + SF_FLOATS*4)

typedef uint32_t u32;
typedef unsigned long long u64;

// ---- device staging (prep -> main) ----
__device__ __align__(16) u64 g_Bfrag[160 * 32];   // frag f = wid*20 + kc*4 + t
__device__ float g_bc[256];
__device__ float g_w2p[128];
__device__ float g_Mg[128];
__device__ float g_M2[4];
__device__ float g_cv[2];
__device__ float g_cg[2];
__device__ float g_wse4[32];
__device__ float g_bse2[16];

// ---- helpers ----
__device__ __forceinline__ u32 f16pack(float a, float b) {
    __half2 h = __floats2half2_rn(a, b);    // a -> low, b -> high
    return *(u32*)&h;
}
__device__ __forceinline__ void mma16816(float* d, const u32* a, u32 b0, u32 b1) {
    asm volatile("mma.sync.aligned.m16n8k16.row.col.f32.f16.f16.f32 "
        "{%0,%1,%2,%3}, {%4,%5,%6,%7}, {%8,%9}, {%0,%1,%2,%3};"
        : "+f"(d[0]), "+f"(d[1]), "+f"(d[2]), "+f"(d[3])
        : "r"(a[0]), "r"(a[1]), "r"(a[2]), "r"(a[3]), "r"(b0), "r"(b1));
}
__device__ __forceinline__ void ldsm_x4(u32* a, u32 addr) {
    asm volatile("ldmatrix.sync.aligned.m8n8.x4.shared.b16 {%0,%1,%2,%3}, [%4];"
        : "=r"(a[0]), "=r"(a[1]), "=r"(a[2]), "=r"(a[3]) : "r"(addr));
}
__device__ __forceinline__ float tanh_hw(float x) {
    float r; asm("tanh.approx.f32 %0, %1;" : "=f"(r) : "f"(x)); return r;
}
__device__ __forceinline__ float lstm_unit(float iv, float fv, float gv, float ov, float& cst) {
    float si = fmaf(0.5f, tanh_hw(0.5f * iv), 0.5f);
    float sf = fmaf(0.5f, tanh_hw(0.5f * fv), 0.5f);
    float tg = tanh_hw(gv);
    float so = fmaf(0.5f, tanh_hw(0.5f * ov), 0.5f);
    float cn = fmaf(sf, cst, si * tg);
    cst = cn;
    return so * tanh_hw(cn);
}

// ============================================================================
// Prep: fold small matrices; build B fragments (fp16, per-warp-slice order)
// ============================================================================
__global__ void prep_kernel(const float* __restrict__ W_ih, const float* __restrict__ W_hh,
                            const float* __restrict__ b_ih, const float* __restrict__ b_hh,
                            const float* __restrict__ W_h2p, const float* __restrict__ b_h2p,
                            const float* __restrict__ W_goal, const float* __restrict__ b_goal,
                            const float* __restrict__ W_abs, const float* __restrict__ b_abs,
                            const float* __restrict__ W_se, const float* __restrict__ b_se)
{
    int tid = threadIdx.x;
    // frag f = w*20 + kc*4 + t  (w = warp slice 0..7, j in [8w, 8w+8))
    for (int idx = tid; idx < 160 * 32; idx += NTHR) {
        int f = idx >> 5, l = idx & 31;
        int w = f / 20, r = f % 20, kc = r >> 2, t = r & 3;
        int jj = l >> 2, c4 = l & 3;
        int j = 8 * w + jj;
        int row = t * 64 + j;
        int k0 = 16 * kc + 2 * c4;
        float v[4];
        #pragma unroll
        for (int i = 0; i < 4; i++) {
            int k = k0 + (i & 1) + (i >> 1) * 8;
            v[i] = (k < 64) ? W_hh[row * 64 + k] : W_ih[row * 16 + (k - 64)];
        }
        __half2 p0 = __floats2half2_rn(v[0], v[1]);
        __half2 p1 = __floats2half2_rn(v[2], v[3]);
        g_Bfrag[idx] = (u64)*(u32*)&p0 | ((u64)*(u32*)&p1 << 32);
    }
    {
        int j = tid & 63, t = tid >> 6, row = t * 64 + j;
        g_bc[tid] = b_ih[row] + b_hh[row];
    }
    if (tid < 64) {
        g_w2p[2 * tid]     = W_h2p[tid];
        g_w2p[2 * tid + 1] = W_h2p[192 + tid];
    }
    if (tid < 128) {
        int r = tid >> 6, j = tid & 63;
        float s = 0.f;
        for (int m = 0; m < 64; m++) s += W_h2p[r * 192 + 128 + m] * W_goal[m * 64 + j];
        g_Mg[tid] = s;
    }
    if (tid < 4) {
        int r = tid >> 1, c = tid & 1;
        float s = 0.f;
        for (int m = 0; m < 64; m++) s += W_h2p[r * 192 + 64 + m] * W_abs[m * 2 + c];
        g_M2[tid] = s;
    }
    if (tid < 2) {
        float s = b_h2p[tid];
        for (int m = 0; m < 64; m++) s += W_h2p[tid * 192 + 64 + m] * b_abs[m];
        g_cv[tid] = s;
        float s2 = 0.f;
        for (int m = 0; m < 64; m++) s2 += W_h2p[tid * 192 + 128 + m] * b_goal[m];
        g_cg[tid] = s2;
    }
    if (tid < 8) {
        g_wse4[tid * 4 + 0] = W_se[(2 * tid) * 2 + 0];
        g_wse4[tid * 4 + 1] = W_se[(2 * tid) * 2 + 1];
        g_wse4[tid * 4 + 2] = W_se[(2 * tid + 1) * 2 + 0];
        g_wse4[tid * 4 + 3] = W_se[(2 * tid + 1) * 2 + 1];
        g_bse2[tid * 2 + 0] = b_se[2 * tid];
        g_bse2[tid * 2 + 1] = b_se[2 * tid + 1];
    }
}

// ============================================================================
// Main kernel: 64 elems/CTA, 8 warps, 2 CTAs/SM, B in registers
// ============================================================================
__global__ void __launch_bounds__(NTHR, 2)
lstm_main(const float* __restrict__ traj_abs, const float* __restrict__ traj_rel,
          const float* __restrict__ h0g, const float* __restrict__ c0g,
          const float* __restrict__ goals, float* __restrict__ out, int Btot)
{
    extern __shared__ __align__(16) char smem[];
    float* sF = (float*)(smem + SM_F);
    const int tid = threadIdx.x, l = tid & 31, wid = tid >> 5;
    const int c4 = l & 3, q = l >> 2;
    const int b0 = blockIdx.x * TB;

    // ---- fill sF from staging ----
    for (int i = tid; i < 256; i += NTHR) sF[FI_BC + i] = g_bc[i];
    if (tid < 128) { sF[FI_W2P + tid] = g_w2p[tid]; sF[FI_MG + tid] = g_Mg[tid]; }
    if (tid < 4)  sF[FI_M2 + tid] = g_M2[tid];
    if (tid < 2)  { sF[FI_CV + tid] = g_cv[tid]; sF[FI_CG + tid] = g_cg[tid]; }
    if (tid < 32) sF[FI_WSE4 + tid] = g_wse4[tid];
    if (tid < 16) sF[FI_BSE2 + tid] = g_bse2[tid];
    __syncthreads();

    // ---- B fragments into registers (persistent) ----
    u64 Breg[5][4];
    {
        const u64* gB = g_Bfrag + (size_t)wid * 20 * 32 + l;
        #pragma unroll
        for (int kc = 0; kc < 5; kc++)
            #pragma unroll
            for (int t = 0; t < 4; t++)
                Breg[kc][t] = gB[(kc * 4 + t) * 32];
    }
    // per-warp-lane constants: biases + w2 pairs for j0 = 8*wid + 2*c4
    const int j0 = 8 * wid + 2 * c4;
    const float2 bI = *(const float2*)(sF + FI_BC + j0);
    const float2 bF = *(const float2*)(sF + FI_BC + 64 + j0);
    const float2 bG = *(const float2*)(sF + FI_BC + 128 + j0);
    const float2 bO = *(const float2*)(sF + FI_BC + 192 + j0);
    const float4 w2q = *(const float4*)(sF + FI_W2P + 2 * j0);
    const int wp = 4 * wid + c4;            // h' store word position (plain)

    // u32 shared base of H buffers
    const u32 Hbase = (u32)__cvta_generic_to_shared(smem);

    // per-mm offsets (m = (mm+wid)&3 stagger)
    int aofs[4], hoff[4], roff[4];
    {
        const int lrow_loc = ((l >> 3) & 1) * 8 + (l & 7);
        const int khalf = l >> 4;
        #pragma unroll
        for (int mm = 0; mm < 4; mm++) {
            int m = (mm + wid) & 3;
            aofs[mm] = (16 * m + lrow_loc) * (HROW * 4) + khalf * 16;
            hoff[mm] = (16 * m + q) * HROW + wp;
            roff[mm] = 16 * m + q;
        }
    }

    // ---- init H buffer 0 (plain fp16x2 word layout) ----
    {
        u32* H0 = (u32*)(smem + SM_H);
        for (int idx = tid; idx < TB * 32; idx += NTHR) {
            int row = idx >> 5, w = idx & 31;
            float2 hv = *(const float2*)(h0g + (size_t)(b0 + row) * 64 + 2 * w);
            H0[row * HROW + w] = f16pack(hv.x, hv.y);
        }
        for (int idx = tid; idx < TB * 8; idx += NTHR) {
            int row = idx >> 3, p = idx & 7;
            float2 tr = *(const float2*)(traj_rel + (size_t)(b0 + row) * 2);
            float4 w4 = *(const float4*)(sF + FI_WSE4 + 4 * p);
            float xa = w4.x * tr.x + w4.y * tr.y + sF[FI_BSE2 + 2 * p];
            float xb = w4.z * tr.x + w4.w * tr.y + sF[FI_BSE2 + 2 * p + 1];
            xa = (xa > 0.f) ? xa : 0.01f * xa;
            xb = (xb > 0.f) ? xb : 0.01f * xb;
            H0[row * HROW + 32 + p] = f16pack(xa, xb);
        }
    }

    // ---- c-state: creg[mm][rh][jj] ----
    float creg[4][2][2];
    #pragma unroll
    for (int mm = 0; mm < 4; mm++)
        #pragma unroll
        for (int rh = 0; rh < 2; rh++) {
            int row = roff[mm] + 8 * rh;
            float2 cv2 = *(const float2*)(c0g + (size_t)(b0 + row) * 64 + j0);
            creg[mm][rh][0] = cv2.x; creg[mm][rh][1] = cv2.y;
        }

    // ---- row-owner derived state (goal fold) -> SMEM (tid < 64, row = tid) ----
    if (tid < TB) {
        const int row = tid;
        float s0 = sF[FI_CG], s1 = sF[FI_CG + 1];
        const float* gp = goals + (size_t)(b0 + row) * 64;
        #pragma unroll 8
        for (int k = 0; k < 64; k++) {
            float gv = gp[k];
            s0 += sF[FI_MG + k] * gv;
            s1 += sF[FI_MG + 64 + k] * gv;
        }
        sF[FI_GOC + 2 * row] = s0; sF[FI_GOC + 2 * row + 1] = s1;
    }
    __syncthreads();

    // ---- tail state in registers ----
    const int trow = tid >> 2;           // tail: row owned by this thread
    const int tpart = tid & 3;           // tail: which partial pair
    const float cv0 = sF[FI_CV], cv1 = sF[FI_CV + 1];
    const float m200 = sF[FI_M2], m201 = sF[FI_M2 + 1];
    const float m210 = sF[FI_M2 + 2], m211 = sF[FI_M2 + 3];
    const float goc0 = sF[FI_GOC + 2 * trow], goc1 = sF[FI_GOC + 2 * trow + 1];
    const float4 wse_a = *(const float4*)(sF + FI_WSE4 + 4 * (2 * tpart));
    const float4 wse_b = *(const float4*)(sF + FI_WSE4 + 4 * (2 * tpart + 1));
    const float2 bse_a = *(const float2*)(sF + FI_BSE2 + 2 * (2 * tpart));
    const float2 bse_b = *(const float2*)(sF + FI_BSE2 + 2 * (2 * tpart + 1));
    // abs-position: private per tail thread (all 4 parts update identically)
    float ab0 = traj_abs[(size_t)(b0 + trow) * 2];
    float ab1 = traj_abs[(size_t)(b0 + trow) * 2 + 1];

    #pragma unroll 1
    for (int s = 0; s < SEQ; s++) {
        const u32 Hu = Hbase + (s & 1) * HBUF_BYTES;
        u32* N = (u32*)(smem + SM_H) + ((s + 1) & 1) * (HBUF_BYTES / 4);

        #pragma unroll
        for (int mm = 0; mm < 4; mm++) {
            // ---- A fragments via ldmatrix.x4 (5 per m-tile) ----
            u32 A[5][4];
            {
                const u32 ab = Hu + aofs[mm];
                #pragma unroll
                for (int kc = 0; kc < 5; kc++)
                    ldsm_x4(A[kc], ab + kc * 32);
            }
            // ---- MMA: bias-initialized accumulators ----
            float acc[4][4] = {
                { bI.x, bI.y, bI.x, bI.y },
                { bF.x, bF.y, bF.x, bF.y },
                { bG.x, bG.y, bG.x, bG.y },
                { bO.x, bO.y, bO.x, bO.y },
            };
            #pragma unroll
            for (int kc = 0; kc < 5; kc++)
                #pragma unroll
                for (int t = 0; t < 4; t++)
                    mma16816(acc[t], A[kc], (u32)Breg[kc][t], (u32)(Breg[kc][t] >> 32));

            // ---- epilogue ----
            float rpm[2][2];
            #pragma unroll
            for (int rh = 0; rh < 2; rh++) {
                float h0v = lstm_unit(acc[0][2 * rh], acc[1][2 * rh],
                                      acc[2][2 * rh], acc[3][2 * rh], creg[mm][rh][0]);
                float h1v = lstm_unit(acc[0][2 * rh + 1], acc[1][2 * rh + 1],
                                      acc[2][2 * rh + 1], acc[3][2 * rh + 1], creg[mm][rh][1]);
                rpm[rh][0] = w2q.x * h0v + w2q.z * h1v;
                rpm[rh][1] = w2q.y * h0v + w2q.w * h1v;
                N[hoff[mm] + 8 * HROW * rh] = f16pack(h0v, h1v);
            }
            // quad butterfly -> warp partial for this warp's 8 j's
            #pragma unroll
            for (int rh = 0; rh < 2; rh++) {
                #pragma unroll
                for (int ax = 0; ax < 2; ax++) {
                    float v = rpm[rh][ax];
                    v += __shfl_xor_sync(0xFFFFFFFFu, v, 1);
                    v += __shfl_xor_sync(0xFFFFFFFFu, v, 2);
                    rpm[rh][ax] = v;
                }
            }
            if (c4 == 0) {
                #pragma unroll
                for (int rh = 0; rh < 2; rh++) {
                    int row = roff[mm] + 8 * rh;
                    *(float2*)(sF + FI_RELP + wid * RELPW + 2 * row) =
                        make_float2(rpm[rh][0], rpm[rh][1]);
                }
            }
        }
        __syncthreads();   // barrier A: h' + RELP visible

        // ---- rel finalization: 4 threads per row (row=tid>>2, part=tid&3) ----
        {
            float2 pa = *(const float2*)(sF + FI_RELP + (2 * tpart) * RELPW + 2 * trow);
            float2 pb = *(const float2*)(sF + FI_RELP + (2 * tpart + 1) * RELPW + 2 * trow);
            float r0 = pa.x + pb.x, r1 = pa.y + pb.y;
            r0 += __shfl_xor_sync(0xFFFFFFFFu, r0, 1);
            r0 += __shfl_xor_sync(0xFFFFFFFFu, r0, 2);
            r1 += __shfl_xor_sync(0xFFFFFFFFu, r1, 1);
            r1 += __shfl_xor_sync(0xFFFFFFFFu, r1, 2);
            r0 += cv0 + goc0 + m200 * ab0 + m201 * ab1;
            r1 += cv1 + goc1 + m210 * ab0 + m211 * ab1;
            if (tpart == 0)
                *(float2*)(out + ((size_t)s * Btot + b0 + trow) * 2) = make_float2(r0, r1);
            ab0 += r0; ab1 += r1;
            if (s < SEQ - 1) {
                float xa = wse_a.x * r0 + wse_a.y * r1 + bse_a.x;
                float xb = wse_a.z * r0 + wse_a.w * r1 + bse_a.y;
                xa = (xa > 0.f) ? xa : 0.01f * xa;
                xb = (xb > 0.f) ? xb : 0.01f * xb;
                N[trow * HROW + 32 + 2 * tpart] = f16pack(xa, xb);
                float xc = wse_b.x * r0 + wse_b.y * r1 + bse_b.x;
                float xd = wse_b.z * r0 + wse_b.w * r1 + bse_b.y;
                xc = (xc > 0.f) ? xc : 0.01f * xc;
                xd = (xd > 0.f) ? xd : 0.01f * xd;
                N[trow * HROW + 32 + 2 * tpart + 1] = f16pack(xc, xd);
            }
        }
        __syncthreads();   // barrier B: x' visible before next step's A loads
    }
}

// ============================================================================
extern "C" void kernel_launch(void* const* d_in, const int* in_sizes, int n_in,
                              void* d_out, int out_size)
{
    const float* traj_abs = (const float*)d_in[0];
    const float* traj_rel = (const float*)d_in[1];
    const float* h0       = (const float*)d_in[2];
    const float* c0       = (const float*)d_in[3];
    const float* goals    = (const float*)d_in[4];
    const float* W_ih     = (const float*)d_in[5];
    const float* W_hh     = (const float*)d_in[6];
    const float* b_ih     = (const float*)d_in[7];
    const float* b_hh     = (const float*)d_in[8];
    const float* W_se     = (const float*)d_in[9];
    const float* b_se     = (const float*)d_in[10];
    const float* W_h2p    = (const float*)d_in[11];
    const float* b_h2p    = (const float*)d_in[12];
    const float* W_goal   = (const float*)d_in[13];
    const float* b_goal   = (const float*)d_in[14];
    const float* W_abs    = (const float*)d_in[15];
    const float* b_abs    = (const float*)d_in[16];

    int B = in_sizes[2] / 64;

    cudaFuncSetAttribute(lstm_main, cudaFuncAttributeMaxDynamicSharedMemorySize, SMEM_BYTES);

    prep_kernel<<<1, NTHR>>>(W_ih, W_hh, b_ih, b_hh, W_h2p, b_h2p,
                             W_goal, b_goal, W_abs, b_abs, W_se, b_se);
    lstm_main<<<B / TB, NTHR, SMEM_BYTES>>>(traj_abs, traj_rel, h0, c0, goals,
                                            (float*)d_out, B);
}